// round 1
// baseline (speedup 1.0000x reference)
#include <cuda_runtime.h>
#include <cuda_bf16.h>
#include <math.h>

// DetectionLoss: B=16, P=16384, T=128, C=80 (derived from in_sizes at launch).
// Stage 1: per-pred argmax IoU over T true boxes + masked smooth-L1 partials.
// Stage 2: deterministic reduction + class loss (log-softmax on row 0) -> scalar.

#define THREADS 256
#define BPRED 2
#define PREDS_PER_BLOCK (THREADS * BPRED)   // 512
#define T_FIXED 128
#define MAX_PARTIALS 8192

__device__ float g_psum[MAX_PARTIALS];
__device__ int   g_pcnt[MAX_PARTIALS];

__device__ __forceinline__ float smooth_l1(float d) {
    float ad = fabsf(d);
    return (ad < 1.0f) ? 0.5f * d * d : ad - 0.5f;
}

__global__ __launch_bounds__(THREADS)
void iou_match_kernel(const float* __restrict__ pred_bboxes,
                      const float* __restrict__ true_bboxes,
                      int P, int T, int blocksPerBatch)
{
    const int b     = blockIdx.x / blocksPerBatch;
    const int chunk = blockIdx.x % blocksPerBatch;
    const int p0    = chunk * PREDS_PER_BLOCK + threadIdx.x;

    __shared__ float4 s_t[T_FIXED];
    __shared__ float  s_ta[T_FIXED];

    const float4* tb = (const float4*)true_bboxes + (size_t)b * T;
    for (int i = threadIdx.x; i < T; i += THREADS) {
        float4 v = tb[i];
        s_t[i]  = v;
        s_ta[i] = (v.z - v.x) * (v.w - v.y);
    }
    __syncthreads();

    const float4* pb = (const float4*)pred_bboxes + (size_t)b * P;

    float4 p[BPRED];
    float  pa[BPRED];
    float  best[BPRED];
    int    bidx[BPRED];
    bool   valid[BPRED];

    #pragma unroll
    for (int j = 0; j < BPRED; j++) {
        int idx  = p0 + j * THREADS;
        valid[j] = (idx < P);
        int lidx = valid[j] ? idx : 0;
        p[j]  = pb[lidx];
        pa[j] = (p[j].z - p[j].x) * (p[j].w - p[j].y);
        best[j] = -1e30f;
        bidx[j] = 0;
    }

    #pragma unroll 4
    for (int t = 0; t < T; t++) {
        float4 tv = s_t[t];
        float  ta = s_ta[t];
        #pragma unroll
        for (int j = 0; j < BPRED; j++) {
            float x1 = fmaxf(p[j].x, tv.x);
            float y1 = fmaxf(p[j].y, tv.y);
            float x2 = fminf(p[j].z, tv.z);
            float y2 = fminf(p[j].w, tv.w);
            float iw = fmaxf(x2 - x1, 0.0f);
            float ih = fmaxf(y2 - y1, 0.0f);
            float inter = iw * ih;
            float uni   = pa[j] + ta - inter;
            float iou   = __fdividef(inter, uni);
            if (iou > best[j]) { best[j] = iou; bidx[j] = t; }
        }
    }

    float lsum = 0.0f;
    int   lcnt = 0;
    #pragma unroll
    for (int j = 0; j < BPRED; j++) {
        if (valid[j] && best[j] > 0.5f) {
            float4 m = s_t[bidx[j]];
            lsum += smooth_l1(p[j].x - m.x) + smooth_l1(p[j].y - m.y)
                  + smooth_l1(p[j].z - m.z) + smooth_l1(p[j].w - m.w);
            lcnt++;
        }
    }

    // Deterministic block reduction: warp shuffle, then smem across warps.
    const unsigned FULL = 0xFFFFFFFFu;
    #pragma unroll
    for (int off = 16; off > 0; off >>= 1) {
        lsum += __shfl_down_sync(FULL, lsum, off);
        lcnt += __shfl_down_sync(FULL, lcnt, off);
    }
    __shared__ float s_ws[THREADS / 32];
    __shared__ int   s_wc[THREADS / 32];
    int lane = threadIdx.x & 31;
    int wid  = threadIdx.x >> 5;
    if (lane == 0) { s_ws[wid] = lsum; s_wc[wid] = lcnt; }
    __syncthreads();
    if (threadIdx.x == 0) {
        float bs = 0.0f; int bc = 0;
        #pragma unroll
        for (int w = 0; w < THREADS / 32; w++) { bs += s_ws[w]; bc += s_wc[w]; }
        g_psum[blockIdx.x] = bs;
        g_pcnt[blockIdx.x] = bc;
    }
}

__global__ __launch_bounds__(256)
void finalize_kernel(const float* __restrict__ pred_classes,
                     const void*  __restrict__ labels_raw,
                     float* __restrict__ out,
                     int nPartials, int P, int T, int C, int B)
{
    __shared__ float s_sum[256];
    __shared__ int   s_cnt[256];
    __shared__ float s_cls[64];
    __shared__ int   s_is64;

    int tid = threadIdx.x;
    float acc = 0.0f; int cnt = 0;
    for (int i = tid; i < nPartials; i += 256) { acc += g_psum[i]; cnt += g_pcnt[i]; }
    s_sum[tid] = acc; s_cnt[tid] = cnt;

    if (tid == 0) {
        // Detect whether labels are int64 or int32: for int64 non-negative
        // values every odd 32-bit word is 0; for int32 labels in [0,80) the
        // odd words are labels themselves (prob of all-zero ~ (1/80)^128 = 0).
        const int* w = (const int*)labels_raw;
        int lim = 2 * B * T;            // 32-bit words if int64
        if (lim > 256) lim = 256;
        int is64 = 1;
        for (int i = 1; i < lim; i += 2) {
            if (w[i] != 0) { is64 = 0; break; }
        }
        s_is64 = is64;
    }
    __syncthreads();

    #pragma unroll
    for (int s = 128; s > 0; s >>= 1) {
        if (tid < s) { s_sum[tid] += s_sum[tid + s]; s_cnt[tid] += s_cnt[tid + s]; }
        __syncthreads();
    }

    // Class loss: logits = pred_classes[b, 0, :], label = true_labels[b, 0]
    if (tid < B && tid < 64) {
        int b = tid;
        int label;
        if (s_is64) label = (int)((const long long*)labels_raw)[(size_t)b * T];
        else        label = ((const int*)labels_raw)[(size_t)b * T];
        const float* lg = pred_classes + (size_t)b * P * C;
        float m = -1e30f;
        for (int c = 0; c < C; c++) m = fmaxf(m, lg[c]);
        float se = 0.0f;
        for (int c = 0; c < C; c++) se += expf(lg[c] - m);
        float logp = lg[label] - m - logf(se);
        s_cls[b] = -logp;
    }
    __syncthreads();

    if (tid == 0) {
        float cls = 0.0f;
        for (int b = 0; b < B; b++) cls += s_cls[b];
        cls /= (float)B;
        float n = (float)s_cnt[0];
        float bbox = s_sum[0] / fmaxf(4.0f * n, 1.0f);
        out[0] = bbox + cls;
    }
}

extern "C" void kernel_launch(void* const* d_in, const int* in_sizes, int n_in,
                              void* d_out, int out_size)
{
    const float* pred_bboxes  = (const float*)d_in[0];
    const float* pred_classes = (const float*)d_in[1];
    const float* true_bboxes  = (const float*)d_in[2];
    const void*  true_labels  = (const void*)d_in[3];

    const int T = T_FIXED;                       // fixed by problem family
    int B = in_sizes[3] / T;                     // true_labels is (B, T)
    if (B < 1) B = 1;
    int P = in_sizes[0] / (4 * B);               // pred_bboxes is (B, P, 4)
    int C = in_sizes[1] / (B * P);               // pred_classes is (B, P, C)

    int blocksPerBatch = (P + PREDS_PER_BLOCK - 1) / PREDS_PER_BLOCK;
    int grid = B * blocksPerBatch;
    if (grid > MAX_PARTIALS) grid = MAX_PARTIALS;  // safety (never hit for these shapes)

    iou_match_kernel<<<grid, THREADS>>>(pred_bboxes, true_bboxes, P, T, blocksPerBatch);
    finalize_kernel<<<1, 256>>>(pred_classes, true_labels, (float*)d_out,
                                grid, P, T, C, B);
}

// round 2
// speedup vs baseline: 1.0545x; 1.0545x over previous
#include <cuda_runtime.h>
#include <cuda_bf16.h>
#include <math.h>

// DetectionLoss fused single-kernel: B=16, P=16384, T=128, C=80.
// Per-block: argmax-IoU match + masked smooth-L1 partial sums.
// Last block (threadfence-reduction pattern): deterministic global reduction,
// label-dtype sniff, per-batch log-softmax class loss, scalar output.

#define THREADS 256
#define BPRED 2
#define PREDS_PER_BLOCK (THREADS * BPRED)   // 512
#define T_FIXED 128
#define MAX_PARTIALS 8192

__device__ float        g_psum[MAX_PARTIALS];
__device__ int          g_pcnt[MAX_PARTIALS];
__device__ unsigned int g_count = 0;

__device__ __forceinline__ float smooth_l1(float d) {
    float ad = fabsf(d);
    return (ad < 1.0f) ? 0.5f * d * d : ad - 0.5f;
}

__global__ __launch_bounds__(THREADS)
void detloss_kernel(const float* __restrict__ pred_bboxes,
                    const float* __restrict__ true_bboxes,
                    const float* __restrict__ pred_classes,
                    const void*  __restrict__ labels_raw,
                    float* __restrict__ out,
                    int P, int T, int C, int B, int blocksPerBatch)
{
    const int b     = blockIdx.x / blocksPerBatch;
    const int chunk = blockIdx.x % blocksPerBatch;
    const int p0    = chunk * PREDS_PER_BLOCK + threadIdx.x;

    __shared__ float4 s_t[T_FIXED];
    __shared__ float  s_ta[T_FIXED];
    __shared__ float  s_ws[THREADS / 32];
    __shared__ int    s_wc[THREADS / 32];
    __shared__ unsigned s_islast;
    __shared__ float  s_cls[32];

    const float4* tb = (const float4*)true_bboxes + (size_t)b * T;
    for (int i = threadIdx.x; i < T; i += THREADS) {
        float4 v = tb[i];
        s_t[i]  = v;
        s_ta[i] = (v.z - v.x) * (v.w - v.y);
    }
    __syncthreads();

    const float4* pb = (const float4*)pred_bboxes + (size_t)b * P;

    float4 p[BPRED];
    float  pa[BPRED];
    float  best[BPRED];
    int    bidx[BPRED];
    bool   valid[BPRED];

    #pragma unroll
    for (int j = 0; j < BPRED; j++) {
        int idx  = p0 + j * THREADS;
        valid[j] = (idx < P);
        int lidx = valid[j] ? idx : 0;
        p[j]  = pb[lidx];
        pa[j] = (p[j].z - p[j].x) * (p[j].w - p[j].y);
        best[j] = -1e30f;
        bidx[j] = 0;
    }

    #pragma unroll 4
    for (int t = 0; t < T; t++) {
        float4 tv = s_t[t];
        float  ta = s_ta[t];
        #pragma unroll
        for (int j = 0; j < BPRED; j++) {
            float x1 = fmaxf(p[j].x, tv.x);
            float y1 = fmaxf(p[j].y, tv.y);
            float x2 = fminf(p[j].z, tv.z);
            float y2 = fminf(p[j].w, tv.w);
            float iw = fmaxf(x2 - x1, 0.0f);
            float ih = fmaxf(y2 - y1, 0.0f);
            float inter = iw * ih;
            float uni   = pa[j] + ta - inter;
            float iou   = __fdividef(inter, uni);
            if (iou > best[j]) { best[j] = iou; bidx[j] = t; }
        }
    }

    float lsum = 0.0f;
    int   lcnt = 0;
    #pragma unroll
    for (int j = 0; j < BPRED; j++) {
        if (valid[j] && best[j] > 0.5f) {
            float4 m = s_t[bidx[j]];
            lsum += smooth_l1(p[j].x - m.x) + smooth_l1(p[j].y - m.y)
                  + smooth_l1(p[j].z - m.z) + smooth_l1(p[j].w - m.w);
            lcnt++;
        }
    }

    // Deterministic block reduction: warp shuffle, then across warps via smem.
    const unsigned FULL = 0xFFFFFFFFu;
    #pragma unroll
    for (int off = 16; off > 0; off >>= 1) {
        lsum += __shfl_down_sync(FULL, lsum, off);
        lcnt += __shfl_down_sync(FULL, lcnt, off);
    }
    int lane = threadIdx.x & 31;
    int wid  = threadIdx.x >> 5;
    if (lane == 0) { s_ws[wid] = lsum; s_wc[wid] = lcnt; }
    __syncthreads();

    if (threadIdx.x == 0) {
        float bs = 0.0f; int bc = 0;
        #pragma unroll
        for (int w = 0; w < THREADS / 32; w++) { bs += s_ws[w]; bc += s_wc[w]; }
        g_psum[blockIdx.x] = bs;
        g_pcnt[blockIdx.x] = bc;
        __threadfence();
        unsigned t = atomicAdd(&g_count, 1u);
        s_islast = (t == gridDim.x - 1) ? 1u : 0u;
    }
    __syncthreads();
    if (!s_islast) return;

    // ---------- Last block: finalize ----------
    const int tid = threadIdx.x;
    const int nP  = gridDim.x;

    // 1) Reduce per-block partials (deterministic fixed order).
    float acc = 0.0f; int cnt = 0;
    for (int i = tid; i < nP; i += THREADS) { acc += g_psum[i]; cnt += g_pcnt[i]; }
    #pragma unroll
    for (int off = 16; off > 0; off >>= 1) {
        acc += __shfl_down_sync(FULL, acc, off);
        cnt += __shfl_down_sync(FULL, cnt, off);
    }
    if (lane == 0) { s_ws[wid] = acc; s_wc[wid] = cnt; }

    // 2) Label dtype sniff, parallel: for int64 (non-negative values) every odd
    //    32-bit word is zero; for int32 labels in [0,C) the odd words are labels
    //    themselves (prob of 128 consecutive odd-position labels all == 0 is ~0).
    int BT = B * T;
    int nz = 0;
    if (tid < 128) {
        int idx = 2 * tid + 1;
        if (idx < BT) nz = (((const int*)labels_raw)[idx] != 0);
    }
    int any32 = __syncthreads_or(nz);   // also acts as a barrier for s_ws/s_wc
    int is64  = !any32;

    // 3) Class loss: one 16-lane half-warp per batch, log-softmax on row 0.
    if (tid < 32) s_cls[tid] = 0.0f;
    __syncthreads();
    int h = tid >> 4;        // half-warp id 0..15
    int l = tid & 15;
    for (int bb = h; bb < B; bb += 16) {
        const float* lg = pred_classes + (size_t)bb * P * C;
        float m = -1e30f;
        for (int c = l; c < C; c += 16) m = fmaxf(m, lg[c]);
        #pragma unroll
        for (int k = 8; k > 0; k >>= 1) m = fmaxf(m, __shfl_xor_sync(FULL, m, k));
        float se = 0.0f;
        for (int c = l; c < C; c += 16) se += __expf(lg[c] - m);
        #pragma unroll
        for (int k = 8; k > 0; k >>= 1) se += __shfl_xor_sync(FULL, se, k);
        if (l == 0) {
            int label = is64 ? (int)((const long long*)labels_raw)[(size_t)bb * T]
                             : ((const int*)labels_raw)[(size_t)bb * T];
            s_cls[bb & 31] = -(lg[label] - m - __logf(se));
        }
    }
    __syncthreads();

    if (tid == 0) {
        float bs = 0.0f; int bc = 0;
        #pragma unroll
        for (int w = 0; w < THREADS / 32; w++) { bs += s_ws[w]; bc += s_wc[w]; }
        float cls = 0.0f;
        for (int bb = 0; bb < B && bb < 32; bb++) cls += s_cls[bb];
        cls /= (float)B;
        float n    = (float)bc;
        float bbox = bs / fmaxf(4.0f * n, 1.0f);
        out[0]  = bbox + cls;
        g_count = 0;   // reset for next graph replay
    }
}

extern "C" void kernel_launch(void* const* d_in, const int* in_sizes, int n_in,
                              void* d_out, int out_size)
{
    const float* pred_bboxes  = (const float*)d_in[0];
    const float* pred_classes = (const float*)d_in[1];
    const float* true_bboxes  = (const float*)d_in[2];
    const void*  true_labels  = (const void*)d_in[3];

    const int T = T_FIXED;                       // fixed by problem family
    int B = in_sizes[3] / T;                     // true_labels is (B, T)
    if (B < 1) B = 1;
    int P = in_sizes[0] / (4 * B);               // pred_bboxes is (B, P, 4)
    int C = in_sizes[1] / (B * P);               // pred_classes is (B, P, C)

    int blocksPerBatch = (P + PREDS_PER_BLOCK - 1) / PREDS_PER_BLOCK;
    int grid = B * blocksPerBatch;
    if (grid > MAX_PARTIALS) grid = MAX_PARTIALS;  // never hit for these shapes

    detloss_kernel<<<grid, THREADS>>>(pred_bboxes, true_bboxes, pred_classes,
                                      true_labels, (float*)d_out,
                                      P, T, C, B, blocksPerBatch);
}

// round 3
// speedup vs baseline: 1.1834x; 1.1223x over previous
#include <cuda_runtime.h>
#include <cuda_bf16.h>
#include <math.h>

// DetectionLoss fused single-kernel: B=16, P=16384, T=128, C=80.
// R3: finer grid (1024 blocks of 128 thr) for occupancy + wave balance;
// encoded argmax (index in low mantissa bits, IMNMX) to cut alu ops.

#define THREADS 128
#define BPRED 2
#define PREDS_PER_BLOCK (THREADS * BPRED)   // 256
#define T_FIXED 128
#define MAX_PARTIALS 8192

__device__ float        g_psum[MAX_PARTIALS];
__device__ int          g_pcnt[MAX_PARTIALS];
__device__ unsigned int g_count = 0;

__device__ __forceinline__ float smooth_l1(float d) {
    float ad = fabsf(d);
    return (ad < 1.0f) ? 0.5f * d * d : ad - 0.5f;
}

__global__ __launch_bounds__(THREADS, 12)
void detloss_kernel(const float* __restrict__ pred_bboxes,
                    const float* __restrict__ true_bboxes,
                    const float* __restrict__ pred_classes,
                    const void*  __restrict__ labels_raw,
                    float* __restrict__ out,
                    int P, int T, int C, int B, int blocksPerBatch)
{
    const int b     = blockIdx.x / blocksPerBatch;
    const int chunk = blockIdx.x % blocksPerBatch;
    const int p0    = chunk * PREDS_PER_BLOCK + threadIdx.x;

    __shared__ float4 s_t[T_FIXED];
    __shared__ float  s_ta[T_FIXED];
    __shared__ float  s_ws[THREADS / 32];
    __shared__ int    s_wc[THREADS / 32];
    __shared__ unsigned s_islast;
    __shared__ float  s_cls[32];

    const float4* tb = (const float4*)true_bboxes + (size_t)b * T;
    for (int i = threadIdx.x; i < T; i += THREADS) {
        float4 v = tb[i];
        s_t[i]  = v;
        s_ta[i] = (v.z - v.x) * (v.w - v.y);
    }
    __syncthreads();

    const float4* pb = (const float4*)pred_bboxes + (size_t)b * P;

    float4 p[BPRED];
    float  pa[BPRED];
    int    best[BPRED];      // encoded: (iou_bits & ~127) | t   (signed int order)
    bool   valid[BPRED];

    #pragma unroll
    for (int j = 0; j < BPRED; j++) {
        int idx  = p0 + j * THREADS;
        valid[j] = (idx < P);
        int lidx = valid[j] ? idx : 0;
        p[j]  = pb[lidx];
        pa[j] = (p[j].z - p[j].x) * (p[j].w - p[j].y);
        best[j] = 0x80000000;   // == encoded(-0.0f, t=0): loses to everything
    }

    #pragma unroll 4
    for (int t = 0; t < T; t++) {
        float4 tv = s_t[t];
        float  ta = s_ta[t];
        #pragma unroll
        for (int j = 0; j < BPRED; j++) {
            float x1 = fmaxf(p[j].x, tv.x);
            float y1 = fmaxf(p[j].y, tv.y);
            float x2 = fminf(p[j].z, tv.z);
            float y2 = fminf(p[j].w, tv.w);
            float iw = fmaxf(x2 - x1, 0.0f);
            float ih = fmaxf(y2 - y1, 0.0f);
            float inter = iw * ih;
            float uni   = (pa[j] + ta) - inter;
            float iou   = __fdividef(inter, uni);
            int enc = (__float_as_int(iou) & (int)0xFFFFFF80) | t;  // LOP3 (imm t)
            best[j] = max(best[j], enc);                            // IMNMX
        }
    }

    float lsum = 0.0f;
    int   lcnt = 0;
    #pragma unroll
    for (int j = 0; j < BPRED; j++) {
        float bf = __int_as_float(best[j] & (int)0xFFFFFF80);
        if (valid[j] && bf > 0.5f) {
            float4 m = s_t[best[j] & 127];
            lsum += smooth_l1(p[j].x - m.x) + smooth_l1(p[j].y - m.y)
                  + smooth_l1(p[j].z - m.z) + smooth_l1(p[j].w - m.w);
            lcnt++;
        }
    }

    // Deterministic block reduction: warp shuffle, then across warps via smem.
    const unsigned FULL = 0xFFFFFFFFu;
    #pragma unroll
    for (int off = 16; off > 0; off >>= 1) {
        lsum += __shfl_down_sync(FULL, lsum, off);
        lcnt += __shfl_down_sync(FULL, lcnt, off);
    }
    int lane = threadIdx.x & 31;
    int wid  = threadIdx.x >> 5;
    if (lane == 0) { s_ws[wid] = lsum; s_wc[wid] = lcnt; }
    __syncthreads();

    if (threadIdx.x == 0) {
        float bs = 0.0f; int bc = 0;
        #pragma unroll
        for (int w = 0; w < THREADS / 32; w++) { bs += s_ws[w]; bc += s_wc[w]; }
        g_psum[blockIdx.x] = bs;
        g_pcnt[blockIdx.x] = bc;
        __threadfence();
        unsigned t = atomicAdd(&g_count, 1u);
        s_islast = (t == gridDim.x - 1) ? 1u : 0u;
    }
    __syncthreads();
    if (!s_islast) return;

    // ---------- Last block: finalize ----------
    const int tid = threadIdx.x;
    const int nP  = gridDim.x;

    // 1) Reduce per-block partials (deterministic fixed order).
    float acc = 0.0f; int cnt = 0;
    for (int i = tid; i < nP; i += THREADS) { acc += g_psum[i]; cnt += g_pcnt[i]; }
    #pragma unroll
    for (int off = 16; off > 0; off >>= 1) {
        acc += __shfl_down_sync(FULL, acc, off);
        cnt += __shfl_down_sync(FULL, cnt, off);
    }
    if (lane == 0) { s_ws[wid] = acc; s_wc[wid] = cnt; }

    // 2) Label dtype sniff (int64 vs int32): int64 non-negative => odd 32-bit
    //    words all zero; int32 labels in [0,C) make odd words nonzero w.h.p.
    int BT = B * T;
    int nz = 0;
    {
        int idx = 2 * tid + 1;
        if (idx < BT) nz = (((const int*)labels_raw)[idx] != 0);
    }
    int any32 = __syncthreads_or(nz);   // also a barrier for s_ws/s_wc
    int is64  = !any32;

    // 3) Class loss: one 16-lane half-warp per batch, log-softmax on row 0.
    if (tid < 32) s_cls[tid] = 0.0f;
    __syncthreads();
    int h = tid >> 4;        // half-warp id 0..7
    int l = tid & 15;
    for (int bb = h; bb < B; bb += THREADS / 16) {
        const float* lg = pred_classes + (size_t)bb * P * C;
        float m = -1e30f;
        for (int c = l; c < C; c += 16) m = fmaxf(m, lg[c]);
        #pragma unroll
        for (int k = 8; k > 0; k >>= 1) m = fmaxf(m, __shfl_xor_sync(FULL, m, k));
        float se = 0.0f;
        for (int c = l; c < C; c += 16) se += __expf(lg[c] - m);
        #pragma unroll
        for (int k = 8; k > 0; k >>= 1) se += __shfl_xor_sync(FULL, se, k);
        if (l == 0) {
            int label = is64 ? (int)((const long long*)labels_raw)[(size_t)bb * T]
                             : ((const int*)labels_raw)[(size_t)bb * T];
            s_cls[bb & 31] = -(lg[label] - m - __logf(se));
        }
    }
    __syncthreads();

    if (tid == 0) {
        float bs = 0.0f; int bc = 0;
        #pragma unroll
        for (int w = 0; w < THREADS / 32; w++) { bs += s_ws[w]; bc += s_wc[w]; }
        float cls = 0.0f;
        for (int bb = 0; bb < B && bb < 32; bb++) cls += s_cls[bb];
        cls /= (float)B;
        float n    = (float)bc;
        float bbox = bs / fmaxf(4.0f * n, 1.0f);
        out[0]  = bbox + cls;
        g_count = 0;   // reset for next graph replay
    }
}

extern "C" void kernel_launch(void* const* d_in, const int* in_sizes, int n_in,
                              void* d_out, int out_size)
{
    const float* pred_bboxes  = (const float*)d_in[0];
    const float* pred_classes = (const float*)d_in[1];
    const float* true_bboxes  = (const float*)d_in[2];
    const void*  true_labels  = (const void*)d_in[3];

    const int T = T_FIXED;                       // fixed by problem family
    int B = in_sizes[3] / T;                     // true_labels is (B, T)
    if (B < 1) B = 1;
    int P = in_sizes[0] / (4 * B);               // pred_bboxes is (B, P, 4)
    int C = in_sizes[1] / (B * P);               // pred_classes is (B, P, C)

    int blocksPerBatch = (P + PREDS_PER_BLOCK - 1) / PREDS_PER_BLOCK;
    int grid = B * blocksPerBatch;
    if (grid > MAX_PARTIALS) grid = MAX_PARTIALS;  // never hit for these shapes

    detloss_kernel<<<grid, THREADS>>>(pred_bboxes, true_bboxes, pred_classes,
                                      true_labels, (float*)d_out,
                                      P, T, C, B, blocksPerBatch);
}